// round 8
// baseline (speedup 1.0000x reference)
#include <cuda_runtime.h>
#include <cstdint>

// Q3 unpack -> float32 planes.
// Input:  4096x4096 int32; each word holds 10 x 3-bit fields at shifts 27..0.
// Output: [10*4096, 4096] f32; plane k = (float)((w >> (27-3k)) & 7), same
// linear layout as input at element offset k * n_words.
//
// R6 (re-run after infra failure): default-policy stores (no .cs) so L2 can
// aggregate dirty lines into larger DRAM write bursts; .cs kept on loads only.
// 16 words/thread: 4 x LDG.128 in, 2 x st.global.v8.b32 per plane out
// (2KB/warp/plane).

__device__ __forceinline__ void stg_v8(float* p, const unsigned int* v)
{
    asm volatile(
        "st.global.v8.b32 [%0], {%1, %2, %3, %4, %5, %6, %7, %8};"
        :: "l"(p),
           "r"(v[0]), "r"(v[1]), "r"(v[2]), "r"(v[3]),
           "r"(v[4]), "r"(v[5]), "r"(v[6]), "r"(v[7])
        : "memory");
}

__global__ void __launch_bounds__(256)
q3_unpack_f32_x16_kernel(const uint4* __restrict__ in,
                         float* __restrict__ out,
                         int ntile)  // number of 16-word tiles (= words/16)
{
    int i = blockIdx.x * blockDim.x + threadIdx.x;
    if (i >= ntile) return;

    uint4 w[4];
#pragma unroll
    for (int j = 0; j < 4; ++j)
        w[j] = __ldcs(in + 4 * (size_t)i + j);

    const unsigned int* ws = (const unsigned int*)w;  // 16 packed words

    const size_t plane = (size_t)ntile * 16;  // plane stride in floats
    float* o = out + (size_t)i * 16;

#pragma unroll
    for (int k = 0; k < 10; ++k) {
        const int s = 27 - 3 * k;
        unsigned int v[16];
#pragma unroll
        for (int j = 0; j < 16; ++j)
            v[j] = __float_as_uint((float)((ws[j] >> s) & 7u));
        float* p = o + (size_t)k * plane;
        stg_v8(p, v);
        stg_v8(p + 8, v + 8);
    }
}

extern "C" void kernel_launch(void* const* d_in, const int* in_sizes, int n_in,
                              void* d_out, int out_size)
{
    (void)n_in; (void)out_size;
    const int n_words = in_sizes[0];      // 4096*4096 = 16,777,216
    const int ntile   = n_words >> 4;     // 1,048,576

    const uint4* in = (const uint4*)d_in[0];
    float* out = (float*)d_out;

    const int threads = 256;
    const int blocks  = (ntile + threads - 1) / threads;  // 4096
    q3_unpack_f32_x16_kernel<<<blocks, threads>>>(in, out, ntile);
}